// round 8
// baseline (speedup 1.0000x reference)
#include <cuda_runtime.h>

// Closed-form normalization constants.
#define Y00f  0.28209479177387814f    // 1/(2*sqrt(pi))
#define N10f  0.48860251190291992f    // sqrt(3/(4pi))
#define N20f  0.63078313050504001f    // sqrt(5/(4pi))
#define C21f  (-1.09254843059207907f) // -(1/2)*sqrt(15/pi)
#define C22f  0.54627421529603953f    // (1/4)*sqrt(15/pi)
#define K20f  0.35355339059327379f    // 1/(2*sqrt(2))
#define K21f  0.20412414523193152f    // 1/(2*sqrt(6))
#define K30f  0.06415002990995843f    // 1/(9*sqrt(3))
#define K31f  0.04536092116208279f    // sqrt(1/486)
#define K32f  0.02028602047074832f    // sqrt(8/19440)

typedef unsigned long long u64;

__device__ __forceinline__ u64 pk(float lo, float hi) {
    u64 r; asm("mov.b64 %0,{%1,%2};" : "=l"(r) : "f"(lo), "f"(hi)); return r;
}
__device__ __forceinline__ void upk(u64 v, float& lo, float& hi) {
    asm("mov.b64 {%0,%1},%2;" : "=f"(lo), "=f"(hi) : "l"(v));
}
__device__ __forceinline__ u64 f2mul(u64 a, u64 b) {
    u64 d; asm("mul.rn.f32x2 %0,%1,%2;" : "=l"(d) : "l"(a), "l"(b)); return d;
}
__device__ __forceinline__ u64 f2fma(u64 a, u64 b, u64 c) {
    u64 d; asm("fma.rn.f32x2 %0,%1,%2,%3;" : "=l"(d) : "l"(a), "l"(b), "l"(c)); return d;
}
__device__ __forceinline__ u64 f2add(u64 a, u64 b) {
    u64 d; asm("add.rn.f32x2 %0,%1,%2;" : "=l"(d) : "l"(a), "l"(b)); return d;
}

// 15 packed coefficient registers (lo == hi) + 1 scalar (b5s).
struct Co {
    u64 b0, b1n, b1d;
    u64 a2, a3, a4;
    u64 a6, a7, a8;
    u64 w9a, cw, w10, w11, w12m, w13;
    float b5s;
};

// Per-point MUFU-only + imm-FFMA prep.
struct P8 { float r, t, ct, st, cp, sp, l30b, g3c; };

__device__ __forceinline__ P8 prep(float r, float th, float ph, float b5s) {
    P8 p;
    p.r = r;
    __sincosf(th, &p.st, &p.ct);
    __sincosf(ph, &p.sp, &p.cp);
    p.t = __expf(r * (-1.0f / 6.0f));               // e^{-r/6}
    float u = fmaf(r, 4.0f / 9.0f, -4.0f);
    p.l30b = fmaf(u, r, 6.0f) * b5s;                // b5*((4/9)r^2-4r+6)
    p.g3c  = fmaf(r, -4.0f / 9.0f, 8.0f / 3.0f);    // (8/3)-(4/9)r
    return p;
}

// Fully packed evaluation of two points.
__device__ __forceinline__ u64 eval_pair(const P8& p0, const P8& p1, const Co& C) {
    u64 R   = pk(p0.r,    p1.r),    T   = pk(p0.t,   p1.t);
    u64 CT  = pk(p0.ct,   p1.ct),   ST  = pk(p0.st,  p1.st);
    u64 CP  = pk(p0.cp,   p1.cp),   SP  = pk(p0.sp,  p1.sp);
    u64 L30B = pk(p0.l30b, p1.l30b), G3C = pk(p0.g3c, p1.g3c);

    u64 T2 = f2mul(T, T), T3 = f2mul(T2, T), T6 = f2mul(T3, T3);
    u64 R2 = f2mul(R, R);
    u64 SPSP = f2mul(SP, SP), SPCP = f2mul(SP, CP);
    u64 CTCT = f2mul(CT, CT), ST2 = f2mul(ST, ST), CTST = f2mul(CT, ST);

    u64 X1 = f2fma(CT, C.a2, f2mul(ST, f2fma(CP, C.a3, f2mul(SP, C.a4))));
    u64 B3 = f2fma(R, f2add(X1, C.b1n), C.b1d);

    u64 X2 = f2fma(CT, C.a6, f2mul(ST, f2fma(CP, C.a7, f2mul(SP, C.a8))));
    u64 G3 = f2mul(R, G3C);
    u64 P2 = f2fma(G3, X2, L30B);

    u64 Y = f2fma(CP, C.w10, f2mul(SP, C.w11));
    u64 Z = f2fma(SPCP, C.w13, f2mul(SPSP, C.w12m));
    u64 W = f2fma(ST2, Z, f2fma(CTST, Y, f2fma(CTCT, C.w9a, C.cw)));
    u64 B2 = f2fma(R2, W, P2);

    return f2fma(T6, C.b0, f2fma(T3, B3, f2mul(T2, B2)));
}

__global__ __launch_bounds__(128)
void orbital_eval_kernel(const float* __restrict__ pos,
                         const float* __restrict__ coeffs,
                         float* __restrict__ out,
                         int n4, int n) {
    int tid0   = blockIdx.x * blockDim.x + threadIdx.x;
    int stride = gridDim.x * blockDim.x;

    float c[14];
#pragma unroll
    for (int k = 0; k < 14; k++) c[k] = __ldg(&coeffs[k]);

    Co C;
    {
        float b0  =  2.0f * Y00f * c[0];
        float b1  =  Y00f * K20f * c[1];
        float a2  =  N10f * K21f * c[3];
        float a3  = -N10f * K21f * c[4];
        float a4  = -N10f * K21f * c[2];
        float a6  =  N10f * K31f * c[7];
        float a7  = -N10f * K31f * c[8];
        float a8  = -N10f * K31f * c[6];
        float n2  =  N20f * K32f * c[11];
        float q12 =  (4.0f / 9.0f) * C21f * K32f * c[12];
        float q10 =  (4.0f / 9.0f) * C21f * K32f * c[10];
        float e13 =  (4.0f / 9.0f) * C22f * K32f * c[13];
        float e9  =  (8.0f / 9.0f) * C22f * K32f * c[9];
        float w9a = (2.0f / 3.0f) * n2 - e13;
        float cw  = -(2.0f / 9.0f) * n2 + e13;
        C.b0  = pk(b0, b0);
        C.b1n = pk(-b1, -b1);
        C.b1d = pk(2.0f * b1, 2.0f * b1);
        C.a2 = pk(a2, a2); C.a3 = pk(a3, a3); C.a4 = pk(a4, a4);
        C.a6 = pk(a6, a6); C.a7 = pk(a7, a7); C.a8 = pk(a8, a8);
        C.w9a = pk(w9a, w9a); C.cw = pk(cw, cw);
        C.w10 = pk(q12, q12); C.w11 = pk(q10, q10);
        C.w12m = pk(-2.0f * e13, -2.0f * e13); C.w13 = pk(e9, e9);
        C.b5s = Y00f * K30f * c[5];
    }

    const float4* p4 = reinterpret_cast<const float4*>(pos);
    float4* o4       = reinterpret_cast<float4*>(out);

    int i = tid0;
    if (i < n4) {
        // Depth-2 software pipeline: two iterations of loads in flight.
        float4 v0 = p4[3 * i + 0];
        float4 v1 = p4[3 * i + 1];
        float4 v2 = p4[3 * i + 2];

        int j = i + stride;
        bool havej = (j < n4);
        float4 w0, w1, w2;
        if (havej) {
            w0 = p4[3 * j + 0];
            w1 = p4[3 * j + 1];
            w2 = p4[3 * j + 2];
        }

        while (true) {
            int kk = j + stride;
            bool havek = havej && (kk < n4);
            float4 u0, u1, u2;
            if (havek) {
                u0 = p4[3 * kk + 0];
                u1 = p4[3 * kk + 1];
                u2 = p4[3 * kk + 2];
            }

            // Evaluate 4 points of iteration i.
            P8 q0 = prep(v0.x, v0.y, v0.z, C.b5s);
            P8 q1 = prep(v0.w, v1.x, v1.y, C.b5s);
            u64 r01 = eval_pair(q0, q1, C);
            P8 q2 = prep(v1.z, v1.w, v2.x, C.b5s);
            P8 q3 = prep(v2.y, v2.z, v2.w, C.b5s);
            u64 r23 = eval_pair(q2, q3, C);

            float4 o;
            upk(r01, o.x, o.y);
            upk(r23, o.z, o.w);
            __stcs(&o4[i], o);

            if (!havej) break;
            v0 = w0; v1 = w1; v2 = w2;
            i = j;
            if (havek) { w0 = u0; w1 = u1; w2 = u2; }
            j = kk;
            havej = havek;
        }
    }

    // Scalar tail (n % 4 != 0).
    int tail = n - n4 * 4;
    if (tid0 < tail) {
        int idx = n4 * 4 + tid0;
        P8 p = prep(pos[3 * idx], pos[3 * idx + 1], pos[3 * idx + 2], C.b5s);
        u64 rr = eval_pair(p, p, C);
        float lo, hi; upk(rr, lo, hi);
        out[idx] = lo;
    }
}

extern "C" void kernel_launch(void* const* d_in, const int* in_sizes, int n_in,
                              void* d_out, int out_size) {
    const float* pos    = (const float*)d_in[0];   // (2048, 4096, 3) fp32
    const float* coeffs = (const float*)d_in[1];   // (14,) fp32
    float* out          = (float*)d_out;           // (2048, 4096) fp32

    int n  = out_size;
    int n4 = n / 4;

    const int threads = 128;
    const int iters   = 8;   // grid-stride iterations per thread
    long long groups  = (n4 > 0) ? n4 : 1;
    int blocks = (int)((groups + (long long)threads * iters - 1) / ((long long)threads * iters));
    if (blocks < 1) blocks = 1;

    orbital_eval_kernel<<<blocks, threads>>>(pos, coeffs, out, n4, n);
}

// round 9
// speedup vs baseline: 1.0790x; 1.0790x over previous
#include <cuda_runtime.h>

// Closed-form normalization constants.
#define Y00f  0.28209479177387814f    // 1/(2*sqrt(pi))
#define N10f  0.48860251190291992f    // sqrt(3/(4pi))
#define N20f  0.63078313050504001f    // sqrt(5/(4pi))
#define C21f  (-1.09254843059207907f) // -(1/2)*sqrt(15/pi)
#define C22f  0.54627421529603953f    // (1/4)*sqrt(15/pi)
#define K20f  0.35355339059327379f    // 1/(2*sqrt(2))
#define K21f  0.20412414523193152f    // 1/(2*sqrt(6))
#define K30f  0.06415002990995843f    // 1/(9*sqrt(3))
#define K31f  0.04536092116208279f    // sqrt(1/486)
#define K32f  0.02028602047074832f    // sqrt(8/19440)

typedef unsigned long long u64;

__device__ u64   g_A[15];   // packed combined coefficients (lo == hi)
__device__ float g_b5;      // scalar L30 coefficient

__device__ __forceinline__ u64 pk(float lo, float hi) {
    u64 r; asm("mov.b64 %0,{%1,%2};" : "=l"(r) : "f"(lo), "f"(hi)); return r;
}
__device__ __forceinline__ void upk(u64 v, float& lo, float& hi) {
    asm("mov.b64 {%0,%1},%2;" : "=f"(lo), "=f"(hi) : "l"(v));
}
__device__ __forceinline__ u64 f2mul(u64 a, u64 b) {
    u64 d; asm("mul.rn.f32x2 %0,%1,%2;" : "=l"(d) : "l"(a), "l"(b)); return d;
}
__device__ __forceinline__ u64 f2fma(u64 a, u64 b, u64 c) {
    u64 d; asm("fma.rn.f32x2 %0,%1,%2,%3;" : "=l"(d) : "l"(a), "l"(b), "l"(c)); return d;
}
__device__ __forceinline__ u64 f2add(u64 a, u64 b) {
    u64 d; asm("add.rn.f32x2 %0,%1,%2;" : "=l"(d) : "l"(a), "l"(b)); return d;
}

// One-warp setup: fold all norms/scalings into 15 packed coefficients.
__global__ void setup_coeffs_kernel(const float* __restrict__ coeffs) {
    if (threadIdx.x == 0) {
        float c[14];
#pragma unroll
        for (int k = 0; k < 14; k++) c[k] = coeffs[k];
        float b0  =  2.0f * Y00f * c[0];
        float b1  =  Y00f * K20f * c[1];
        float a2  =  N10f * K21f * c[3];
        float a3  = -N10f * K21f * c[4];
        float a4  = -N10f * K21f * c[2];
        float a6  =  N10f * K31f * c[7];
        float a7  = -N10f * K31f * c[8];
        float a8  = -N10f * K31f * c[6];
        float n2  =  N20f * K32f * c[11];
        float q12 =  (4.0f / 9.0f) * C21f * K32f * c[12];
        float q10 =  (4.0f / 9.0f) * C21f * K32f * c[10];
        float e13 =  (4.0f / 9.0f) * C22f * K32f * c[13];
        float e9  =  (8.0f / 9.0f) * C22f * K32f * c[9];
        float w9a = (2.0f / 3.0f) * n2 - e13;   // ct^2 coefficient
        float cw  = -(2.0f / 9.0f) * n2 + e13;  // constant term
        float v[15] = { b0, -b1, 2.0f * b1, a2, a3, a4, a6, a7, a8,
                        w9a, cw, q12, q10, -2.0f * e13, e9 };
#pragma unroll
        for (int k = 0; k < 15; k++) g_A[k] = pk(v[k], v[k]);
        g_b5 = Y00f * K30f * c[5];
    }
}

// Per-point prep: MUFU + imm-FFMA only.
struct P8 { float r, t, ct, st, cp, sp, l30b, g3c; };

__device__ __forceinline__ P8 prep(float r, float th, float ph, float b5s) {
    P8 p;
    p.r = r;
    __sincosf(th, &p.st, &p.ct);
    __sincosf(ph, &p.sp, &p.cp);
    p.t = __expf(r * (-1.0f / 6.0f));               // e^{-r/6}
    float u = fmaf(r, 4.0f / 9.0f, -4.0f);
    p.l30b = fmaf(u, r, 6.0f) * b5s;                // b5*((4/9)r^2-4r+6)
    p.g3c  = fmaf(r, -4.0f / 9.0f, 8.0f / 3.0f);    // (8/3)-(4/9)r
    return p;
}

// Fully packed evaluation of two points; coefficients loaded at use sites
// so ptxas can rematerialize them as L1 broadcast hits (keeps regs low).
__device__ __forceinline__ u64 eval_pair(const P8& p0, const P8& p1,
                                         const u64* __restrict__ A) {
    u64 R   = pk(p0.r,    p1.r),    T   = pk(p0.t,   p1.t);
    u64 CT  = pk(p0.ct,   p1.ct),   ST  = pk(p0.st,  p1.st);
    u64 CP  = pk(p0.cp,   p1.cp),   SP  = pk(p0.sp,  p1.sp);
    u64 L30B = pk(p0.l30b, p1.l30b), G3C = pk(p0.g3c, p1.g3c);

    u64 T2 = f2mul(T, T), T3 = f2mul(T2, T), T6 = f2mul(T3, T3);
    u64 R2 = f2mul(R, R);
    u64 SPSP = f2mul(SP, SP), SPCP = f2mul(SP, CP);
    u64 CTCT = f2mul(CT, CT), ST2 = f2mul(ST, ST), CTST = f2mul(CT, ST);

    // n=2 block: B3 = r*(X1 + b1n) + b1d
    u64 X1 = f2fma(CT, __ldg(&A[3]),
                   f2mul(ST, f2fma(CP, __ldg(&A[4]), f2mul(SP, __ldg(&A[5])))));
    u64 B3 = f2fma(R, f2add(X1, __ldg(&A[1])), __ldg(&A[2]));

    // n=3 l=0..1: P2 = L30B + r*g3c*X2
    u64 X2 = f2fma(CT, __ldg(&A[6]),
                   f2mul(ST, f2fma(CP, __ldg(&A[7]), f2mul(SP, __ldg(&A[8])))));
    u64 G3 = f2mul(R, G3C);
    u64 P2 = f2fma(G3, X2, L30B);

    // n=3 l=2 (4/9 scaling folded into coefficients):
    u64 Y = f2fma(CP, __ldg(&A[11]), f2mul(SP, __ldg(&A[12])));
    u64 Z = f2fma(SPCP, __ldg(&A[14]), f2mul(SPSP, __ldg(&A[13])));
    u64 W = f2fma(ST2, Z, f2fma(CTST, Y, f2fma(CTCT, __ldg(&A[9]), __ldg(&A[10]))));
    u64 B2 = f2fma(R2, W, P2);

    return f2fma(T6, __ldg(&A[0]), f2fma(T3, B3, f2mul(T2, B2)));
}

__global__ __launch_bounds__(128)
void orbital_eval_kernel(const float* __restrict__ pos,
                         float* __restrict__ out,
                         int n4, int n) {
    int i = blockIdx.x * blockDim.x + threadIdx.x;

    const u64* A = g_A;
    float b5s = __ldg(&g_b5);

    if (i < n4) {
        const float4* p4 = reinterpret_cast<const float4*>(pos);
        // 3 front-batched 128-bit loads: 4 points.
        float4 v0 = p4[3 * i + 0];
        float4 v1 = p4[3 * i + 1];
        float4 v2 = p4[3 * i + 2];

        P8 q0 = prep(v0.x, v0.y, v0.z, b5s);
        P8 q1 = prep(v0.w, v1.x, v1.y, b5s);
        u64 r01 = eval_pair(q0, q1, A);
        P8 q2 = prep(v1.z, v1.w, v2.x, b5s);
        P8 q3 = prep(v2.y, v2.z, v2.w, b5s);
        u64 r23 = eval_pair(q2, q3, A);

        float4 o;
        upk(r01, o.x, o.y);
        upk(r23, o.z, o.w);
        __stcs(reinterpret_cast<float4*>(out) + i, o);
    }

    // Scalar tail (n % 4 != 0).
    int tail = n - n4 * 4;
    if (i < tail) {
        int idx = n4 * 4 + i;
        P8 p = prep(pos[3 * idx], pos[3 * idx + 1], pos[3 * idx + 2], b5s);
        u64 rr = eval_pair(p, p, A);
        float lo, hi; upk(rr, lo, hi);
        out[idx] = lo;
    }
}

extern "C" void kernel_launch(void* const* d_in, const int* in_sizes, int n_in,
                              void* d_out, int out_size) {
    const float* pos    = (const float*)d_in[0];   // (2048, 4096, 3) fp32
    const float* coeffs = (const float*)d_in[1];   // (14,) fp32
    float* out          = (float*)d_out;           // (2048, 4096) fp32

    int n  = out_size;
    int n4 = n / 4;

    setup_coeffs_kernel<<<1, 32>>>(coeffs);

    const int threads = 128;
    int groups = (n4 > 0) ? n4 : 1;
    int blocks = (groups + threads - 1) / threads;
    orbital_eval_kernel<<<blocks, threads>>>(pos, out, n4, n);
}